// round 6
// baseline (speedup 1.0000x reference)
#include <cuda_runtime.h>

// WarpImage R6: horizontal-tap-merged gather.
// Per pixel-row, one aligned LDG.128 (float4 at u0c & ~3) covers both
// horizontal taps for 75% of lanes; a predicated scalar LDG covers the
// wrap case (u0c%4==3 with in-bounds u1). Cuts L1 gather wavefront work
// ~40% vs 4x scalar LDG (the measured ~110us L1 floor of R2/R5).
// Border semantics identical to reference: independently clamped taps,
// out-of-image taps zeroed via weights.

#define CC 32
#define HH 1024
#define WW 2048
#define HWSZ (HH * WW)

struct Px {
    float w00, w10, w01, w11;
    int b0, b1;      // element offsets of aligned float4 in rows v0c, v1c
    int m;           // u0c & 3   (0..3)
    int m2;          // m + du    (0..4; 4 => needs extra scalar load)
    int idx;         // output offset within one channel plane
};

__device__ __forceinline__ Px setup_pixel(const float* __restrict__ flow,
                                          int w, int h)
{
    Px p;
    p.idx = h * WW + w;
    float u = (float)w + __ldg(flow + p.idx);
    float v = (float)h + __ldg(flow + HWSZ + p.idx);

    float u0f = floorf(u);
    float v0f = floorf(v);
    float wu = u - u0f;
    float wv = v - v0f;

    int u0 = (int)u0f;
    int v0 = (int)v0f;

    bool vu0 = (u0 >= 0) && (u0 <= WW - 1);
    bool vu1 = (u0 + 1 >= 0) && (u0 + 1 <= WW - 1);
    bool vv0 = (v0 >= 0) && (v0 <= HH - 1);
    bool vv1 = (v0 + 1 >= 0) && (v0 + 1 <= HH - 1);

    p.w00 = (1.0f - wu) * (1.0f - wv); if (!(vu0 && vv0)) p.w00 = 0.0f;
    p.w10 = wu * (1.0f - wv);          if (!(vu1 && vv0)) p.w10 = 0.0f;
    p.w01 = (1.0f - wu) * wv;          if (!(vu0 && vv1)) p.w01 = 0.0f;
    p.w11 = wu * wv;                   if (!(vu1 && vv1)) p.w11 = 0.0f;

    int u0c = min(max(u0, 0), WW - 1);
    int u1c = min(max(u0 + 1, 0), WW - 1);
    int v0c = min(max(v0, 0), HH - 1);
    int v1c = min(max(v0 + 1, 0), HH - 1);

    int e = u0c & ~3;
    p.m  = u0c & 3;
    p.m2 = p.m + (u1c - u0c);   // u1c - u0c in {0,1}
    p.b0 = v0c * WW + e;
    p.b1 = v1c * WW + e;
    return p;
}

__global__ __launch_bounds__(256) void warp_image_kernel(
    const float* __restrict__ image,
    const float* __restrict__ flow,
    float* __restrict__ out)
{
    const int w = blockIdx.x * 32 + threadIdx.x;
    const int h = blockIdx.y * 8 + threadIdx.y;

    Px p = setup_pixel(flow, w, h);
    const bool xtra = (p.m2 == 4);

    const float* imgc = image;
    float* outc = out;

    #pragma unroll 2
    for (int c = 0; c < CC; c++) {
        float4 A = __ldg((const float4*)(imgc + p.b0));
        float4 B = __ldg((const float4*)(imgc + p.b1));
        float ex0 = 0.0f, ex1 = 0.0f;
        if (xtra) {
            ex0 = __ldg(imgc + p.b0 + 4);
            ex1 = __ldg(imgc + p.b1 + 4);
        }

        float t00 = (p.m == 0) ? A.x : (p.m == 1) ? A.y : (p.m == 2) ? A.z : A.w;
        float t01 = (p.m == 0) ? B.x : (p.m == 1) ? B.y : (p.m == 2) ? B.z : B.w;
        float t10 = (p.m2 == 0) ? A.x : (p.m2 == 1) ? A.y : (p.m2 == 2) ? A.z
                  : (p.m2 == 3) ? A.w : ex0;
        float t11 = (p.m2 == 0) ? B.x : (p.m2 == 1) ? B.y : (p.m2 == 2) ? B.z
                  : (p.m2 == 3) ? B.w : ex1;

        float g = p.w00 * t00 + p.w10 * t10 + p.w01 * t01 + p.w11 * t11;
        outc[p.idx] = g;

        imgc += HWSZ;
        outc += HWSZ;
    }
}

extern "C" void kernel_launch(void* const* d_in, const int* in_sizes, int n_in,
                              void* d_out, int out_size)
{
    const float* image = (const float*)d_in[0];
    const float* flow  = (const float*)d_in[1];
    float* out = (float*)d_out;

    cudaFuncSetAttribute(warp_image_kernel,
                         cudaFuncAttributePreferredSharedMemoryCarveout, 0);

    dim3 block(32, 8);
    dim3 grid(WW / 32, HH / 8);   // (64, 128)
    warp_image_kernel<<<grid, block>>>(image, flow, out);
}

// round 7
// speedup vs baseline: 1.5361x; 1.5361x over previous
#include <cuda_runtime.h>

// WarpImage R7: scalar-gather structure of R2 (best measured: 111us-equiv L1
// work), with the horizontal tap pair merged into one 8B-aligned LDG.64 at
// e2 = u0c & ~1. Even-u0c lanes get both taps from the float2; odd lanes get
// t00 from .y plus one predicated scalar for t10. ~25% less L1 gather work.
// Border semantics: independently clamped taps + weight zeroing (exact
// reference match); du=0 collapses t10->t00 via select.

#define CC 32
#define HH 1024
#define WW 2048
#define HWSZ (HH * WW)

__global__ __launch_bounds__(256) void warp_image_kernel(
    const float* __restrict__ image,
    const float* __restrict__ flow,
    float* __restrict__ out)
{
    const int w = blockIdx.x * 32 + threadIdx.x;
    const int h = blockIdx.y * 8 + threadIdx.y;
    const int idx = h * WW + w;

    float u = (float)w + __ldg(flow + idx);
    float v = (float)h + __ldg(flow + HWSZ + idx);

    float u0f = floorf(u);
    float v0f = floorf(v);
    float wu = u - u0f;
    float wv = v - v0f;

    int u0 = (int)u0f;
    int v0 = (int)v0f;

    bool vu0 = (u0 >= 0) && (u0 <= WW - 1);
    bool vu1 = (u0 + 1 >= 0) && (u0 + 1 <= WW - 1);
    bool vv0 = (v0 >= 0) && (v0 <= HH - 1);
    bool vv1 = (v0 + 1 >= 0) && (v0 + 1 <= HH - 1);

    float w00 = (1.0f - wu) * (1.0f - wv); if (!(vu0 && vv0)) w00 = 0.0f;
    float w10 = wu * (1.0f - wv);          if (!(vu1 && vv0)) w10 = 0.0f;
    float w01 = (1.0f - wu) * wv;          if (!(vu0 && vv1)) w01 = 0.0f;
    float w11 = wu * wv;                   if (!(vu1 && vv1)) w11 = 0.0f;

    int u0c = min(max(u0, 0), WW - 1);
    int u1c = min(max(u0 + 1, 0), WW - 1);
    int v0c = min(max(v0, 0), HH - 1);
    int v1c = min(max(v0 + 1, 0), HH - 1);

    const int  e2  = u0c & ~1;            // 8B-aligned base column
    const bool odd = (u0c & 1) != 0;
    const bool du  = (u1c != u0c);        // horizontal step exists
    const bool xs  = odd && du;           // need extra scalar at e2+2
    const int  b0  = v0c * WW + e2;
    const int  b1  = v1c * WW + e2;

    const float* imgc = image;
    float* outc = out;

    #pragma unroll 4
    for (int c = 0; c < CC; c++) {
        float2 A = __ldg((const float2*)(imgc + b0));
        float2 B = __ldg((const float2*)(imgc + b1));
        float ex0 = 0.0f, ex1 = 0.0f;
        if (xs) {
            ex0 = __ldg(imgc + b0 + 2);
            ex1 = __ldg(imgc + b1 + 2);
        }

        float t00 = odd ? A.y : A.x;
        float t01 = odd ? B.y : B.x;
        float t10 = !du ? t00 : (odd ? ex0 : A.y);
        float t11 = !du ? t01 : (odd ? ex1 : B.y);

        outc[idx] = w00 * t00 + w10 * t10 + w01 * t01 + w11 * t11;

        imgc += HWSZ;
        outc += HWSZ;
    }
}

extern "C" void kernel_launch(void* const* d_in, const int* in_sizes, int n_in,
                              void* d_out, int out_size)
{
    const float* image = (const float*)d_in[0];
    const float* flow  = (const float*)d_in[1];
    float* out = (float*)d_out;

    cudaFuncSetAttribute(warp_image_kernel,
                         cudaFuncAttributePreferredSharedMemoryCarveout, 0);

    dim3 block(32, 8);
    dim3 grid(WW / 32, HH / 8);   // (64, 128)
    warp_image_kernel<<<grid, block>>>(image, flow, out);
}

// round 8
// speedup vs baseline: 1.8519x; 1.2056x over previous
#include <cuda_runtime.h>

// WarpImage R8: scalar 4-tap direct gather (R2 structure — measured-optimal
// L1 economics: divergent gather cost is proportional to bytes/lane, so
// 4x LDG.32 = 16B/lane-ch is the floor), register-tuned to 32 regs for
// ~93% occupancy (R7 demonstrated the util headroom: 84.5% -> 92%+).
// Offsets kept as o00 + du + dvW to minimize live registers.

#define CC 32
#define HH 1024
#define WW 2048
#define HWSZ (HH * WW)

__global__ __launch_bounds__(256, 8) void warp_image_kernel(
    const float* __restrict__ image,
    const float* __restrict__ flow,
    float* __restrict__ out)
{
    const int w = blockIdx.x * 32 + threadIdx.x;
    const int h = blockIdx.y * 8 + threadIdx.y;
    const int idx = h * WW + w;

    float u = (float)w + __ldg(flow + idx);
    float v = (float)h + __ldg(flow + HWSZ + idx);

    float u0f = floorf(u);
    float v0f = floorf(v);
    float wu = u - u0f;
    float wv = v - v0f;

    int u0 = (int)u0f;
    int v0 = (int)v0f;

    bool vu0 = (u0 >= 0) && (u0 <= WW - 1);
    bool vu1 = (u0 + 1 >= 0) && (u0 + 1 <= WW - 1);
    bool vv0 = (v0 >= 0) && (v0 <= HH - 1);
    bool vv1 = (v0 + 1 >= 0) && (v0 + 1 <= HH - 1);

    float w00 = (1.0f - wu) * (1.0f - wv); if (!(vu0 && vv0)) w00 = 0.0f;
    float w10 = wu * (1.0f - wv);          if (!(vu1 && vv0)) w10 = 0.0f;
    float w01 = (1.0f - wu) * wv;          if (!(vu0 && vv1)) w01 = 0.0f;
    float w11 = wu * wv;                   if (!(vu1 && vv1)) w11 = 0.0f;

    int u0c = min(max(u0, 0), WW - 1);
    int v0c = min(max(v0, 0), HH - 1);

    // compact tap addressing: clamp(x+1) = clamp(x) + d
    const int du  = ((u0 >= 0) && (u0 <= WW - 2)) ? 1 : 0;
    const int dvW = ((v0 >= 0) && (v0 <= HH - 2)) ? WW : 0;

    const float* g = image + (v0c * WW + u0c);   // tap (v0,u0), channel 0
    float* o = out + idx;

    #pragma unroll 4
    for (int c = 0; c < CC; c++) {
        float t00 = __ldg(g);
        float t10 = __ldg(g + du);
        float t01 = __ldg(g + dvW);
        float t11 = __ldg(g + dvW + du);
        *o = w00 * t00 + w10 * t10 + w01 * t01 + w11 * t11;
        g += HWSZ;
        o += HWSZ;
    }
}

extern "C" void kernel_launch(void* const* d_in, const int* in_sizes, int n_in,
                              void* d_out, int out_size)
{
    const float* image = (const float*)d_in[0];
    const float* flow  = (const float*)d_in[1];
    float* out = (float*)d_out;

    cudaFuncSetAttribute(warp_image_kernel,
                         cudaFuncAttributePreferredSharedMemoryCarveout, 0);

    dim3 block(32, 8);
    dim3 grid(WW / 32, HH / 8);   // (64, 128)
    warp_image_kernel<<<grid, block>>>(image, flow, out);
}

// round 9
// speedup vs baseline: 1.8801x; 1.0153x over previous
#include <cuda_runtime.h>

// WarpImage R9: R8's scalar 4-tap direct gather (measured-optimal: divergent
// gather L1 cost ~ bytes/lane, 4x LDG.32 = 16B/lane-ch floor; ~110us-equiv
// work at ~85% achievable l1tex util), with 32x16 pixel tiles (512-thread
// blocks) to halve the vertical flow-halo amortization and cut L2->L1 fill
// wavefronts that compete with gathers in l1tex. 32 regs forced via
// __launch_bounds__(512,4) -> full occupancy.

#define CC 32
#define HH 1024
#define WW 2048
#define HWSZ (HH * WW)

__global__ __launch_bounds__(512, 4) void warp_image_kernel(
    const float* __restrict__ image,
    const float* __restrict__ flow,
    float* __restrict__ out)
{
    const int w = blockIdx.x * 32 + threadIdx.x;
    const int h = blockIdx.y * 16 + threadIdx.y;
    const int idx = h * WW + w;

    float u = (float)w + __ldg(flow + idx);
    float v = (float)h + __ldg(flow + HWSZ + idx);

    float u0f = floorf(u);
    float v0f = floorf(v);
    float wu = u - u0f;
    float wv = v - v0f;

    int u0 = (int)u0f;
    int v0 = (int)v0f;

    bool vu0 = (u0 >= 0) && (u0 <= WW - 1);
    bool vu1 = (u0 + 1 >= 0) && (u0 + 1 <= WW - 1);
    bool vv0 = (v0 >= 0) && (v0 <= HH - 1);
    bool vv1 = (v0 + 1 >= 0) && (v0 + 1 <= HH - 1);

    float w00 = (1.0f - wu) * (1.0f - wv); if (!(vu0 && vv0)) w00 = 0.0f;
    float w10 = wu * (1.0f - wv);          if (!(vu1 && vv0)) w10 = 0.0f;
    float w01 = (1.0f - wu) * wv;          if (!(vu0 && vv1)) w01 = 0.0f;
    float w11 = wu * wv;                   if (!(vu1 && vv1)) w11 = 0.0f;

    int u0c = min(max(u0, 0), WW - 1);
    int v0c = min(max(v0, 0), HH - 1);

    // compact tap addressing: clamp(x+1) = clamp(x) + d
    const int du  = ((u0 >= 0) && (u0 <= WW - 2)) ? 1 : 0;
    const int dvW = ((v0 >= 0) && (v0 <= HH - 2)) ? WW : 0;

    const float* g = image + (v0c * WW + u0c);   // tap (v0,u0), channel 0
    float* o = out + idx;

    #pragma unroll 4
    for (int c = 0; c < CC; c++) {
        float t00 = __ldg(g);
        float t10 = __ldg(g + du);
        float t01 = __ldg(g + dvW);
        float t11 = __ldg(g + dvW + du);
        *o = w00 * t00 + w10 * t10 + w01 * t01 + w11 * t11;
        g += HWSZ;
        o += HWSZ;
    }
}

extern "C" void kernel_launch(void* const* d_in, const int* in_sizes, int n_in,
                              void* d_out, int out_size)
{
    const float* image = (const float*)d_in[0];
    const float* flow  = (const float*)d_in[1];
    float* out = (float*)d_out;

    cudaFuncSetAttribute(warp_image_kernel,
                         cudaFuncAttributePreferredSharedMemoryCarveout, 0);

    dim3 block(32, 16);
    dim3 grid(WW / 32, HH / 16);   // (64, 64)
    warp_image_kernel<<<grid, block>>>(image, flow, out);
}